// round 16
// baseline (speedup 1.0000x reference)
#include <cuda_runtime.h>
#include <cuda_fp16.h>
#include <cstdint>

// ============================================================================
// LSTM cell via mma.sync fp16 single-pass (fp32 accum), fused LSTM epilogue.
// B=65536, Din=256, H=512 fixed.
// PERSISTENT kernel: 296 CTAs (2/SM), each processes ~28 tiles of 128x128
// (4 gates x 32 h) with a continuous cp.async stage stream (ring never
// drains across tiles). Mainloop = round-6 validated shape: 8 warps 2Mx4N,
// warp 64x32, BK=64, 3-buffer ring, two syncs per stage, 2 CTAs/SM.
// ============================================================================

#define BATCH 65536
#define DIN   256
#define HH    512
#define BM    128
#define BK    64
#define NSTAGE 12
#define NTILES 8192          // (BATCH/128) * (HH/32)
#define NCTA   296           // 2 * 148 SMs

// ---------------- device scratch --------------------------------------------
__device__ __half g_Xh[BATCH * DIN];
__device__ __half g_Hh[BATCH * HH];
__device__ __half g_Ut[4 * HH * DIN];   // [g][h][k] K-major
__device__ __half g_Wt[4 * HH * HH];
__device__ float  g_bias[4 * HH];        // bU + bW

// ---------------- helpers ----------------------------------------------------
__device__ __forceinline__ uint32_t smem_u32(const void* p) {
    uint32_t a;
    asm("{ .reg .u64 t; cvta.to.shared.u64 t, %1; cvt.u32.u64 %0, t; }"
        : "=r"(a) : "l"(p));
    return a;
}
#define SW128(off) ((off) ^ (((off) >> 3) & 0x70))

__device__ __forceinline__ void cp16(uint32_t dst, const void* src) {
    asm volatile("cp.async.cg.shared.global [%0], [%1], 16;\n" :: "r"(dst), "l"(src));
}
#define CP_COMMIT() asm volatile("cp.async.commit_group;\n" ::: "memory")
#define CP_WAIT2()  asm volatile("cp.async.wait_group 2;\n" ::: "memory")
#define CP_WAIT1()  asm volatile("cp.async.wait_group 1;\n" ::: "memory")
#define CP_WAIT0()  asm volatile("cp.async.wait_group 0;\n" ::: "memory")

#define LDSM_X4(r0, r1, r2, r3, a)                                              \
    asm volatile("ldmatrix.sync.aligned.m8n8.x4.shared.b16 {%0,%1,%2,%3}, [%4];"\
        : "=r"(r0), "=r"(r1), "=r"(r2), "=r"(r3) : "r"(a))

__device__ __forceinline__ void mma16816(float* c, uint32_t a0, uint32_t a1,
                                         uint32_t a2, uint32_t a3,
                                         uint32_t b0, uint32_t b1) {
    asm volatile(
        "mma.sync.aligned.m16n8k16.row.col.f32.f16.f16.f32 "
        "{%0,%1,%2,%3}, {%4,%5,%6,%7}, {%8,%9}, {%0,%1,%2,%3};"
        : "+f"(c[0]), "+f"(c[1]), "+f"(c[2]), "+f"(c[3])
        : "r"(a0), "r"(a1), "r"(a2), "r"(a3), "r"(b0), "r"(b1));
}

// ---------------- SMEM layout ------------------------------------------------
// [0, 512)       bias (4 gates x 32 h floats) for current tile
// [1024, 99328)  3 stage buffers; per stage: A 16KB + B 16KB
// [99328, ...)   epilogue exchange: 16 rows x 132 floats = 8448 B
#define SM_STAGE(b) (1024 + (b) * 32768)
#define EX_BASE     99328
#define EX_ROW      132                   // floats (pad for bank spread)
#define SMEM_TOTAL  (EX_BASE + 16 * EX_ROW * 4)   // 107776

// ---------------- fused pre-pass ---------------------------------------------
// blocks [0,512):   U transpose tiles  (K=256)
// blocks [512,1536): W transpose tiles (K=512)
// blocks [1536, ...): activations fp32->fp16 grid-stride + bias merge
__global__ void pre_kernel(const float* __restrict__ X,
                           const float* __restrict__ H,
                           const float* __restrict__ U,
                           const float* __restrict__ W,
                           const float* __restrict__ bU,
                           const float* __restrict__ bW,
                           __half* __restrict__ Xh,
                           __half* __restrict__ Hh,
                           __half* __restrict__ Ut,
                           __half* __restrict__ Wt) {
    __shared__ float tile[32][33];
    const int bid = blockIdx.x;
    const int tid = threadIdx.x;

    if (bid < 1536) {
        // weight transpose: src [4,K,HH] f32 -> dst [4,HH,K] fp16
        const float* src; __half* dst; int K, g, k0, h0;
        if (bid < 512) {
            K = DIN; src = U; dst = Ut;
            g = bid >> 7; int rem = bid & 127;
            k0 = (rem >> 4) * 32; h0 = (rem & 15) * 32;
        } else {
            K = HH; src = W; dst = Wt;
            int r = bid - 512;
            g = r >> 8; int rem = r & 255;
            k0 = (rem >> 4) * 32; h0 = (rem & 15) * 32;
        }
        const int tx = tid & 31, ty = tid >> 5;
        #pragma unroll
        for (int j = 0; j < 4; j++)
            tile[ty + j * 8][tx] = src[((size_t)g * K + k0 + ty + j * 8) * HH + h0 + tx];
        __syncthreads();
        #pragma unroll
        for (int j = 0; j < 4; j++)
            dst[((size_t)g * HH + h0 + ty + j * 8) * K + k0 + tx] =
                __float2half_rn(tile[tx][ty + j * 8]);
    } else {
        const int n1 = BATCH * DIN / 4;
        const int n2 = BATCH * HH / 4;
        int i = (bid - 1536) * blockDim.x + tid;
        if (i < 2048) g_bias[i] = bU[i] + bW[i];
        const int stride = (gridDim.x - 1536) * blockDim.x;
        for (; i < n1 + n2; i += stride) {
            const float* src = (i < n1) ? X : H;
            __half* dst = (i < n1) ? Xh : Hh;
            int j = (i < n1) ? i : i - n1;
            float4 v = reinterpret_cast<const float4*>(src)[j];
            __half h[4] = {__float2half_rn(v.x), __float2half_rn(v.y),
                           __float2half_rn(v.z), __float2half_rn(v.w)};
            reinterpret_cast<uint2*>(dst)[j] = *reinterpret_cast<uint2*>(h);
        }
    }
}

// ---------------- stage source selection -------------------------------------
__device__ __forceinline__ void stage_src(int s, const __half*& A,
                                          const __half*& Bt, int& K, int& k0) {
    if (s < 4) {
        K = DIN; k0 = s * BK;
        A = g_Xh; Bt = g_Ut;
    } else {
        K = HH; k0 = (s - 4) * BK;
        A = g_Hh; Bt = g_Wt;
    }
}

__device__ __forceinline__ void load_stage(uint32_t smem_base, int buf, int s,
                                           int bm0, int h0, int tid) {
    const __half *A, *Bt;
    int K, k0;
    stage_src(s, A, Bt, K, k0);
    uint32_t abase = smem_base + SM_STAGE(buf);
    // A tile: 128 rows x 64 k (128B/row), SW128 -> 1024 16B chunks
    #pragma unroll
    for (int i = 0; i < 4; i++) {
        int c = tid + i * 256;
        int row = c >> 3, o = c & 7;
        cp16(abase + SW128(row * 128 + o * 16),
             A + (size_t)(bm0 + row) * K + k0 + o * 8);
    }
    // B tile: 128 rows (gate-major: row = g*32 + h_local) x 64 k
    uint32_t bbase = abase + 16384;
    #pragma unroll
    for (int i = 0; i < 4; i++) {
        int c = tid + i * 256;
        int row = c >> 3, o = c & 7;
        int g = row >> 5, hl = row & 31;
        cp16(bbase + SW128(row * 128 + o * 16),
             Bt + ((size_t)g * HH + h0 + hl) * K + k0 + o * 8);
    }
    CP_COMMIT();
}

// ---------------- main kernel -------------------------------------------------
__device__ __forceinline__ float sigmoid_f(float x) { return 1.0f / (1.0f + __expf(-x)); }
__device__ __forceinline__ float tanh_f(float x) {
    float ax = fabsf(x);
    float e = __expf(-2.0f * ax);
    float t = (1.0f - e) / (1.0f + e);
    return (x < 0.0f) ? -t : t;
}

__global__ void __launch_bounds__(256, 2)
lstm_mma_kernel(const float* __restrict__ Cin, float* __restrict__ out) {
    extern __shared__ char smem[];
    uint32_t smem_base = smem_u32(smem);
    float* bias_s = reinterpret_cast<float*>(smem);
    float* ex = reinterpret_cast<float*>(smem + EX_BASE);

    const int tid  = threadIdx.x;
    const int lane = tid & 31;
    const int w    = tid >> 5;
    const int wm   = (w >> 2) * 64;     // warp M offset
    const int nb   = (w & 3) * 32;      // warp N offset == gate*32
    const int bid  = blockIdx.x;

    const int ntiles = (NTILES - bid + NCTA - 1) / NCTA;
    const int total  = ntiles * NSTAGE;

    // tile(p) helpers
    int t_cur = bid;                    // tile for p's tile index
    int h0  = (t_cur & 15) * 32;
    int bm0 = (t_cur >> 4) * BM;

    // prologue: first 3 stages of first tile
    load_stage(smem_base, 0, 0, bm0, h0, tid);
    load_stage(smem_base, 1, 1, bm0, h0, tid);
    load_stage(smem_base, 2, 2, bm0, h0, tid);
    int issued = 3;

    if (tid < 128)
        bias_s[tid] = g_bias[(tid >> 5) * HH + h0 + (tid & 31)];

    float acc[4][4][4];
    #pragma unroll
    for (int mi = 0; mi < 4; mi++)
        #pragma unroll
        for (int nt = 0; nt < 4; nt++)
            #pragma unroll
            for (int j = 0; j < 4; j++)
                acc[mi][nt][j] = 0.0f;

    // per-lane ldmatrix base offsets (bytes within tile, pre-swizzle)
    const int ar = wm + (lane & 15);
    const int aco = (lane >> 4) * 16;
    int offA[4];
    #pragma unroll
    for (int mi = 0; mi < 4; mi++)
        offA[mi] = (ar + mi * 16) * 128 + aco;
    const int grp = lane >> 3;
    const int br = nb + (grp >> 1) * 8 + (lane & 7);
    const int bco = (grp & 1) * 16;
    int offB[2];
    #pragma unroll
    for (int j = 0; j < 2; j++)
        offB[j] = (br + j * 16) * 128 + bco;

    const size_t BHo = (size_t)BATCH * HH;

    for (int p = 0; p < total; p++) {
        // wait for stage p's data
        int ahead = issued - p;     // groups not yet known-complete (incl p)
        if (ahead >= 3) CP_WAIT2();
        else if (ahead == 2) CP_WAIT1();
        else CP_WAIT0();
        __syncthreads();

        // compute stage p from buffer p%3
        uint32_t ab = smem_base + SM_STAGE(p % 3);
        uint32_t bb = ab + 16384;
        #pragma unroll
        for (int ks = 0; ks < 4; ks++) {
            uint32_t a[4][4];
            #pragma unroll
            for (int mi = 0; mi < 4; mi++)
                LDSM_X4(a[mi][0], a[mi][1], a[mi][2], a[mi][3],
                        ab + SW128(offA[mi] + ks * 32));
            uint32_t b[2][4];
            #pragma unroll
            for (int j = 0; j < 2; j++)
                LDSM_X4(b[j][0], b[j][1], b[j][2], b[j][3],
                        bb + SW128(offB[j] + ks * 32));
            #pragma unroll
            for (int mi = 0; mi < 4; mi++)
                #pragma unroll
                for (int nt = 0; nt < 4; nt++)
                    mma16816(acc[mi][nt],
                             a[mi][0], a[mi][1], a[mi][2], a[mi][3],
                             b[nt >> 1][(nt & 1) * 2], b[nt >> 1][(nt & 1) * 2 + 1]);
        }
        __syncthreads();

        // prefetch stage p+3 (possibly next tile's stage) into buffer p%3
        if (p + 3 < total) {
            int pn = p + 3;
            int tn = bid + (pn / NSTAGE) * NCTA;
            load_stage(smem_base, p % 3, pn % NSTAGE,
                       (tn >> 4) * BM, (tn & 15) * 32, tid);
            issued++;
        }

        // tile boundary: epilogue (stage buffers untouched; loads in flight)
        if ((p % NSTAGE) == NSTAGE - 1) {
            // prefetch Cin: 8 rounds x float2 per thread (MLP=8)
            const int rrow = tid >> 4;            // 0..15
            const int hloc = (tid & 15) * 2;      // 0,2,..,30
            float2 cold[8];
            #pragma unroll
            for (int r = 0; r < 8; r++) {
                int m = bm0 + (r >> 2) * 64 + (r & 3) * 16 + rrow;
                cold[r] = *reinterpret_cast<const float2*>(
                    &Cin[(size_t)m * HH + h0 + hloc]);
            }
            #pragma unroll 1
            for (int r = 0; r < 8; r++) {
                const int wr = r >> 2;   // warp-row
                const int mi = r & 3;
                __syncthreads();   // ex free from previous round
                if ((w >> 2) == wr) {
                    #pragma unroll
                    for (int nt = 0; nt < 4; nt++) {
                        int col = nb + nt * 8 + (lane & 3) * 2;
                        int rl  = lane >> 2;
                        *reinterpret_cast<float2*>(&ex[rl * EX_ROW + col]) =
                            make_float2(acc[mi][nt][0], acc[mi][nt][1]);
                        *reinterpret_cast<float2*>(&ex[(rl + 8) * EX_ROW + col]) =
                            make_float2(acc[mi][nt][2], acc[mi][nt][3]);
                    }
                }
                __syncthreads();
                // LSTM update: thread -> row rrow, 2 h columns
                const int m = bm0 + wr * 64 + mi * 16 + rrow;
                float hn[2], cn[2];
                #pragma unroll
                for (int j = 0; j < 2; j++) {
                    int hc = hloc + j;
                    float gi = ex[rrow * EX_ROW + 0 * 32 + hc] + bias_s[0 * 32 + hc];
                    float gf = ex[rrow * EX_ROW + 1 * 32 + hc] + bias_s[1 * 32 + hc];
                    float go = ex[rrow * EX_ROW + 2 * 32 + hc] + bias_s[2 * 32 + hc];
                    float gc = ex[rrow * EX_ROW + 3 * 32 + hc] + bias_s[3 * 32 + hc];
                    float it = sigmoid_f(gi);
                    float ft = sigmoid_f(gf);
                    float ot = sigmoid_f(go);
                    float ct = tanh_f(gc);
                    float cj = (j == 0) ? cold[r].x : cold[r].y;
                    float c  = fmaf(it, ct, ft * cj);
                    cn[j] = c;
                    hn[j] = ot * tanh_f(c);
                }
                *reinterpret_cast<float2*>(&out[(size_t)m * HH + h0 + hloc]) =
                    make_float2(hn[0], hn[1]);
                *reinterpret_cast<float2*>(&out[BHo + (size_t)m * HH + h0 + hloc]) =
                    make_float2(cn[0], cn[1]);
            }

            // advance to next tile: zero accs, reload bias (next epilogue is
            // >= 12 syncs away, so no extra barrier needed for bias)
            #pragma unroll
            for (int mi = 0; mi < 4; mi++)
                #pragma unroll
                for (int nt = 0; nt < 4; nt++)
                    #pragma unroll
                    for (int j = 0; j < 4; j++)
                        acc[mi][nt][j] = 0.0f;
            t_cur += NCTA;
            if (t_cur < NTILES) {
                h0  = (t_cur & 15) * 32;
                bm0 = (t_cur >> 4) * BM;
                if (tid < 128)
                    bias_s[tid] = g_bias[(tid >> 5) * HH + h0 + (tid & 31)];
            }
        }
    }
}

// ---------------- launch ------------------------------------------------------
extern "C" void kernel_launch(void* const* d_in, const int* in_sizes, int n_in,
                              void* d_out, int out_size) {
    const float* X   = (const float*)d_in[0];
    const float* Hin = (const float*)d_in[1];
    const float* Cin = (const float*)d_in[2];
    const float* U   = (const float*)d_in[3];
    const float* bU  = (const float*)d_in[4];
    const float* W   = (const float*)d_in[5];
    const float* bW  = (const float*)d_in[6];
    float* out = (float*)d_out;

    cudaFuncSetAttribute(lstm_mma_kernel,
                         cudaFuncAttributeMaxDynamicSharedMemorySize, SMEM_TOTAL);

    __half *xh, *hh, *ut, *wt;
    cudaGetSymbolAddress((void**)&xh, g_Xh);
    cudaGetSymbolAddress((void**)&hh, g_Hh);
    cudaGetSymbolAddress((void**)&ut, g_Ut);
    cudaGetSymbolAddress((void**)&wt, g_Wt);

    // fused pre-pass: 1536 transpose blocks + 4096 activation blocks
    pre_kernel<<<1536 + 4096, 256>>>(X, Hin, U, W, bU, bW, xh, hh, ut, wt);

    // persistent main kernel: 2 CTAs per SM
    lstm_mma_kernel<<<NCTA, 256, SMEM_TOTAL>>>(Cin, out);
}